// round 12
// baseline (speedup 1.0000x reference)
#include <cuda_runtime.h>
#include <cuda_bf16.h>
#include <cstdint>

// Problem constants (match reference setup_inputs)
#define NN 40000
#define EE 640000
#define GG 64
#define DD 128          // D_IN = D_EMB = D_HID
#define DOUT 36

// ---------------- scratch (device globals; no allocation allowed) -----------
__device__ __align__(16) float g_deg[NN];          // degree, then rsqrt in place
__device__ __align__(16) float g_hW[(size_t)NN * DD];
__device__ __align__(16) int   g_ecnt[NN];         // per-dst edge count
__device__ __align__(16) int   g_fill[NN];         // fill cursors (preloaded = rowstart)
__device__ __align__(16) int   g_rs[NN + 1];       // row starts, g_rs[NN] = EE
__device__ __align__(16) int   g_csrc[EE];         // CSR: src node per slot
__device__ __align__(16) float g_cw[EE];           // CSR: normalized edge weight
__device__ __align__(16) int   g_pmaxi[GG * DD];   // float bits, values >= 0
__device__ __align__(16) float g_psum[GG * DD];
__device__ float g_cnt[GG];

// ---------------- helpers ---------------------------------------------------
__device__ __forceinline__ void red_add_v4(float* p, float a, float b, float c, float d) {
    asm volatile("red.global.add.v4.f32 [%0], {%1, %2, %3, %4};"
                 :: "l"(p), "f"(a), "f"(b), "f"(c), "f"(d) : "memory");
}
__device__ __forceinline__ void red_add_f32(float* p, float v) {
    asm volatile("red.global.add.f32 [%0], %1;" :: "l"(p), "f"(v) : "memory");
}
// packed f32x2 FMA: acc += a * b (elementwise on register pairs) -> SASS FFMA2
__device__ __forceinline__ void ffma2(unsigned long long& acc,
                                      unsigned long long a, unsigned long long b) {
    asm("fma.rn.f32x2 %0, %1, %2, %0;" : "+l"(acc) : "l"(a), "l"(b));
}

// ---------------- kernels ---------------------------------------------------

// reset all per-call state
__global__ void k_init() {
    int i = blockIdx.x * blockDim.x + threadIdx.x;
    if (i < NN) { g_deg[i] = 1.0f; g_ecnt[i] = 0; }
    if (i < GG * DD) { g_pmaxi[i] = 0; g_psum[i] = 0.0f; }
    if (i < GG) g_cnt[i] = 0.0f;
}

// deg[dst] += edge_weight ; histogram counts per dst
__global__ void k_deg(const int* __restrict__ ei, const float* __restrict__ ew) {
    int e = blockIdx.x * blockDim.x + threadIdx.x;
    if (e >= EE) return;
    int dst = ei[EE + e];
    red_add_f32(&g_deg[dst], ew[e]);
    atomicAdd(&g_ecnt[dst], 1);
}

// single-block exclusive scan of 40000 counts (1024 thr x 40 elems) +
// fused deg->rsqrt. Writes g_rs (row starts) and preloads g_fill cursors.
#define PER_T 40
__global__ void k_scan() {
    __shared__ int wsum[32];
    __shared__ int wexc[32];
    const int t = threadIdx.x;
    const int lane = t & 31, wid = t >> 5;
    const int base = t * PER_T;

    int s = 0;
    #pragma unroll
    for (int i = 0; i < PER_T; i++) {
        int idx = base + i;
        s += (idx < NN) ? g_ecnt[idx] : 0;
    }
    // warp inclusive scan of per-thread sums
    int v = s;
    #pragma unroll
    for (int off = 1; off < 32; off <<= 1) {
        int n = __shfl_up_sync(0xffffffffu, v, off);
        if (lane >= off) v += n;
    }
    if (lane == 31) wsum[wid] = v;
    __syncthreads();
    if (wid == 0) {
        int wv = wsum[lane];
        int q = wv;
        #pragma unroll
        for (int off = 1; off < 32; off <<= 1) {
            int n = __shfl_up_sync(0xffffffffu, q, off);
            if (lane >= off) q += n;
        }
        wexc[lane] = q - wv;        // exclusive warp offset
    }
    __syncthreads();

    int run = (v - s) + wexc[wid];  // exclusive prefix for this thread
    #pragma unroll
    for (int i = 0; i < PER_T; i++) {
        int idx = base + i;
        if (idx < NN) {
            g_rs[idx] = run;
            g_fill[idx] = run;
            run += g_ecnt[idx];
        }
    }
    #pragma unroll
    for (int i = 0; i < PER_T; i++) {
        int idx = base + i;
        if (idx < NN) g_deg[idx] = rsqrtf(g_deg[idx]);
    }
    if (t == 0) g_rs[NN] = EE;
}

// scatter edges into CSR slots with precomputed symmetric norm
__global__ void k_fill(const int* __restrict__ ei, const float* __restrict__ ew) {
    int e = blockIdx.x * blockDim.x + threadIdx.x;
    if (e >= EE) return;
    int src = ei[e];
    int dst = ei[EE + e];
    float nrm = g_deg[src] * ew[e] * g_deg[dst];
    int pos = atomicAdd(&g_fill[dst], 1);      // cursor preloaded with row start
    g_csrc[pos] = src;
    g_cw[pos] = nrm;
}

// hW = x @ conv_w  (40000x128 @ 128x128, fp32) using packed f32x2 FFMA2.
// Pairing is over consecutive k (even/odd partial sums, cross-added at the end),
// so both operand pairs come directly from LDS.64 with no packing MOVs.
// Stride 130: lane*130 -> 2*lane banks (conflict-free 64b phases); rows 520 B
// (8-aligned). All smem stores into stride-130 rows use <=8-byte granularity.
#define WT_STR 130
__global__ __launch_bounds__(256, 2)
void k_gemm(const float* __restrict__ X, const float* __restrict__ W) {
    extern __shared__ float smem[];
    float* WTs = smem;                    // [col][k], stride 130
    float* xs  = smem + 128 * WT_STR;     // [row][k], stride 130

    const int tid = threadIdx.x;
    const int row0 = blockIdx.x * 64;

    // load + transpose W (W is [k][c] row-major): scalar smem stores
    {
        const float4* Wg = reinterpret_cast<const float4*>(W);
        #pragma unroll
        for (int i = 0; i < 16; i++) {
            int v = tid + i * 256;
            int k = v >> 5;               // row of W
            int c = (v & 31) << 2;        // starting col
            float4 w4 = Wg[v];
            WTs[(c + 0) * WT_STR + k] = w4.x;
            WTs[(c + 1) * WT_STR + k] = w4.y;
            WTs[(c + 2) * WT_STR + k] = w4.z;
            WTs[(c + 3) * WT_STR + k] = w4.w;
        }
    }
    // load x tile (64 rows x 128): float4 gmem load, 2x float2 smem store
    // (row byte stride 520 is 8-aligned but NOT 16-aligned -> no float4 STS)
    {
        const float4* Xg = reinterpret_cast<const float4*>(X + (size_t)row0 * DD);
        #pragma unroll
        for (int i = 0; i < 8; i++) {
            int v = tid + i * 256;
            int r = v >> 5, q = v & 31;
            float4 x4 = Xg[v];
            float2* p = reinterpret_cast<float2*>(xs + r * WT_STR + 4 * q);
            p[0] = make_float2(x4.x, x4.y);
            p[1] = make_float2(x4.z, x4.w);
        }
    }
    __syncthreads();

    const int lane = tid & 31;
    const int wrp = tid >> 5;             // 8 rows per warp
    const float* xbase = xs + (wrp * 8) * WT_STR;
    const float* wbase = WTs + lane * WT_STR;   // cols lane + 32*cc

    unsigned long long acc[8][4];
    #pragma unroll
    for (int j = 0; j < 8; j++)
        #pragma unroll
        for (int c = 0; c < 4; c++) acc[j][c] = 0ull;

    #pragma unroll 8
    for (int k = 0; k < 128; k += 2) {
        unsigned long long wp[4], xp[8];
        #pragma unroll
        for (int c = 0; c < 4; c++)
            wp[c] = *reinterpret_cast<const unsigned long long*>(wbase + c * 32 * WT_STR + k);
        #pragma unroll
        for (int j = 0; j < 8; j++)
            xp[j] = *reinterpret_cast<const unsigned long long*>(xbase + j * WT_STR + k);
        #pragma unroll
        for (int j = 0; j < 8; j++)
            #pragma unroll
            for (int c = 0; c < 4; c++)
                ffma2(acc[j][c], xp[j], wp[c]);
    }

    // epilogue: cross-add halves, store (coalesced: lane -> col lane+32c)
    #pragma unroll
    for (int j = 0; j < 8; j++) {
        float* orow = g_hW + (size_t)(row0 + wrp * 8 + j) * DD;
        #pragma unroll
        for (int c = 0; c < 4; c++) {
            unsigned long long a = acc[j][c];
            float lo = __uint_as_float((unsigned)(a & 0xffffffffu));
            float hi = __uint_as_float((unsigned)(a >> 32));
            orow[lane + 32 * c] = lo + hi;
        }
    }
}

// fused: CSR gather + self-loop + bias + ReLU + pooled max/sum/cnt.
// one warp per 8 consecutive nodes (batch sorted -> rare flushes).
__device__ __forceinline__ void pool_flush(int g, int lane, float4 pm, float4 ps, int cl) {
    int base = g * DD + lane * 4;
    atomicMax(&g_pmaxi[base + 0], __float_as_int(pm.x));
    atomicMax(&g_pmaxi[base + 1], __float_as_int(pm.y));
    atomicMax(&g_pmaxi[base + 2], __float_as_int(pm.z));
    atomicMax(&g_pmaxi[base + 3], __float_as_int(pm.w));
    red_add_v4(&g_psum[base], ps.x, ps.y, ps.z, ps.w);
    if (lane == 0) red_add_f32(&g_cnt[g], (float)cl);
}

__global__ void k_gather_pool(const float* __restrict__ bias,
                              const int* __restrict__ batchv) {
    int warp = (blockIdx.x * blockDim.x + threadIdx.x) >> 5;
    if (warp >= NN / 8) return;
    const int lane = threadIdx.x & 31;
    const int n0 = warp * 8;

    float4 bia = reinterpret_cast<const float4*>(bias)[lane];
    float4 pm = make_float4(0.f, 0.f, 0.f, 0.f);
    float4 ps = make_float4(0.f, 0.f, 0.f, 0.f);
    int cl = 0;
    int cur_g = batchv[n0];

    #pragma unroll 1
    for (int i = 0; i < 8; i++) {
        int n = n0 + i;
        int g = batchv[n];
        if (g != cur_g) {
            pool_flush(cur_g, lane, pm, ps, cl);
            pm = make_float4(0.f, 0.f, 0.f, 0.f);
            ps = make_float4(0.f, 0.f, 0.f, 0.f);
            cl = 0;
            cur_g = g;
        }
        float dn = g_deg[n];
        float sl = dn * dn;                          // self-loop norm
        float4 h = reinterpret_cast<const float4*>(g_hW + (size_t)n * DD)[lane];
        float4 acc = make_float4(fmaf(h.x, sl, bia.x), fmaf(h.y, sl, bia.y),
                                 fmaf(h.z, sl, bia.z), fmaf(h.w, sl, bia.w));
        int e0 = g_rs[n];
        int e1 = g_rs[n + 1];
        int e = e0;
        for (; e + 4 <= e1; e += 4) {
            int s0 = g_csrc[e],     s1 = g_csrc[e + 1];
            int s2 = g_csrc[e + 2], s3 = g_csrc[e + 3];
            float w0 = g_cw[e],     w1 = g_cw[e + 1];
            float w2 = g_cw[e + 2], w3 = g_cw[e + 3];
            float4 v0 = reinterpret_cast<const float4*>(g_hW + (size_t)s0 * DD)[lane];
            float4 v1 = reinterpret_cast<const float4*>(g_hW + (size_t)s1 * DD)[lane];
            float4 v2 = reinterpret_cast<const float4*>(g_hW + (size_t)s2 * DD)[lane];
            float4 v3 = reinterpret_cast<const float4*>(g_hW + (size_t)s3 * DD)[lane];
            acc.x = fmaf(v0.x, w0, fmaf(v1.x, w1, fmaf(v2.x, w2, fmaf(v3.x, w3, acc.x))));
            acc.y = fmaf(v0.y, w0, fmaf(v1.y, w1, fmaf(v2.y, w2, fmaf(v3.y, w3, acc.y))));
            acc.z = fmaf(v0.z, w0, fmaf(v1.z, w1, fmaf(v2.z, w2, fmaf(v3.z, w3, acc.z))));
            acc.w = fmaf(v0.w, w0, fmaf(v1.w, w1, fmaf(v2.w, w2, fmaf(v3.w, w3, acc.w))));
        }
        for (; e < e1; e++) {
            int s0 = g_csrc[e];
            float w0 = g_cw[e];
            float4 v0 = reinterpret_cast<const float4*>(g_hW + (size_t)s0 * DD)[lane];
            acc.x = fmaf(v0.x, w0, acc.x);
            acc.y = fmaf(v0.y, w0, acc.y);
            acc.z = fmaf(v0.z, w0, acc.z);
            acc.w = fmaf(v0.w, w0, acc.w);
        }
        // ReLU
        acc.x = fmaxf(acc.x, 0.f); acc.y = fmaxf(acc.y, 0.f);
        acc.z = fmaxf(acc.z, 0.f); acc.w = fmaxf(acc.w, 0.f);
        // pool into registers
        pm.x = fmaxf(pm.x, acc.x); pm.y = fmaxf(pm.y, acc.y);
        pm.z = fmaxf(pm.z, acc.z); pm.w = fmaxf(pm.w, acc.w);
        ps.x += acc.x; ps.y += acc.y; ps.z += acc.z; ps.w += acc.w;
        cl++;
    }
    pool_flush(cur_g, lane, pm, ps, cl);
}

// per-graph MLP: one block (128 threads) per graph runs all three layers
__global__ void k_mlp(const float* __restrict__ rho,
                      const float* __restrict__ w1, const float* __restrict__ b1,
                      const float* __restrict__ w2, const float* __restrict__ b2,
                      const float* __restrict__ w3, const float* __restrict__ b3,
                      float* __restrict__ out) {
    __shared__ float hg[260];
    __shared__ float z1[DD];
    __shared__ float z2[DD];
    const int g = blockIdx.x;
    const int t = threadIdx.x;

    float cnt = g_cnt[g];
    float inv = 1.0f / fmaxf(cnt, 1.0f);
    hg[t] = __int_as_float(g_pmaxi[g * DD + t]);
    hg[DD + t] = g_psum[g * DD + t] * inv;
    if (t == 0) hg[2 * DD] = rho[g];
    __syncthreads();

    float acc = b1[t];
    #pragma unroll 8
    for (int k = 0; k < 2 * DD + 1; k++) acc = fmaf(hg[k], w1[k * DD + t], acc);
    z1[t] = fmaxf(acc, 0.f);
    __syncthreads();

    acc = b2[t];
    #pragma unroll 8
    for (int k = 0; k < DD; k++) acc = fmaf(z1[k], w2[k * DD + t], acc);
    z2[t] = fmaxf(acc, 0.f);
    __syncthreads();

    if (t < DOUT) {
        acc = b3[t];
        #pragma unroll 8
        for (int k = 0; k < DD; k++) acc = fmaf(z2[k], w3[k * DOUT + t], acc);
        out[g * DOUT + t] = acc;
    }
}

// ---------------- launch -----------------------------------------------------
extern "C" void kernel_launch(void* const* d_in, const int* in_sizes, int n_in,
                              void* d_out, int out_size) {
    const float* x      = (const float*)d_in[0];
    const float* ew     = (const float*)d_in[1];
    const float* rho    = (const float*)d_in[2];
    const float* conv_w = (const float*)d_in[3];
    const float* conv_b = (const float*)d_in[4];
    const float* w1     = (const float*)d_in[5];
    const float* b1     = (const float*)d_in[6];
    const float* w2     = (const float*)d_in[7];
    const float* b2     = (const float*)d_in[8];
    const float* w3     = (const float*)d_in[9];
    const float* b3     = (const float*)d_in[10];
    const int*   ei     = (const int*)d_in[11];
    const int*   batchv = (const int*)d_in[12];
    float* out = (float*)d_out;

    const int gemm_smem = (128 * WT_STR + 64 * WT_STR) * 4;   // 99840 B
    cudaFuncSetAttribute(k_gemm, cudaFuncAttributeMaxDynamicSharedMemorySize, gemm_smem);

    // reset state
    k_init<<<(NN + 255) / 256, 256>>>();
    // degree + histogram
    k_deg<<<(EE + 255) / 256, 256>>>(ei, ew);
    // single-block scan (also fuses deg->rsqrt, preloads fill cursors)
    k_scan<<<1, 1024>>>();
    // CSR fill with precomputed norms
    k_fill<<<(EE + 255) / 256, 256>>>(ei, ew);
    // hW = x @ conv_w (FFMA2 packed math)
    k_gemm<<<NN / 64, 256, gemm_smem>>>(x, conv_w);
    // fused gather + relu + pool
    k_gather_pool<<<(NN / 8 * 32 + 255) / 256, 256>>>(conv_b, batchv);
    // MLP head
    k_mlp<<<GG, DD>>>(rho, w1, b1, w2, b2, w3, b3, out);
}

// round 13
// speedup vs baseline: 1.0234x; 1.0234x over previous
#include <cuda_runtime.h>
#include <cuda_bf16.h>
#include <cstdint>

// Problem constants (match reference setup_inputs)
#define NN 40000
#define EE 640000
#define GG 64
#define DD 128          // D_IN = D_EMB = D_HID
#define DOUT 36

// ---------------- scratch (device globals; no allocation allowed) -----------
__device__ __align__(16) float g_deg[NN];          // degree, then rsqrt in place
__device__ __align__(16) float g_hW[(size_t)NN * DD];
__device__ __align__(16) int   g_ecnt[NN];         // per-dst edge count
__device__ __align__(16) int   g_fill[NN];         // fill cursors (preloaded = rowstart)
__device__ __align__(16) int   g_rs[NN + 1];       // row starts, g_rs[NN] = EE
__device__ __align__(16) int2  g_edge[EE];         // CSR: {src, norm bits} per slot
__device__ __align__(16) int   g_pmaxi[GG * DD];   // float bits, values >= 0
__device__ __align__(16) float g_psum[GG * DD];
__device__ float g_cnt[GG];

// ---------------- helpers ---------------------------------------------------
__device__ __forceinline__ void red_add_v4(float* p, float a, float b, float c, float d) {
    asm volatile("red.global.add.v4.f32 [%0], {%1, %2, %3, %4};"
                 :: "l"(p), "f"(a), "f"(b), "f"(c), "f"(d) : "memory");
}
__device__ __forceinline__ void red_add_f32(float* p, float v) {
    asm volatile("red.global.add.f32 [%0], %1;" :: "l"(p), "f"(v) : "memory");
}

// ---------------- kernels ---------------------------------------------------

// reset all per-call state
__global__ void k_init() {
    int i = blockIdx.x * blockDim.x + threadIdx.x;
    if (i < NN) { g_deg[i] = 1.0f; g_ecnt[i] = 0; }
    if (i < GG * DD) { g_pmaxi[i] = 0; g_psum[i] = 0.0f; }
    if (i < GG) g_cnt[i] = 0.0f;
}

// deg[dst] += edge_weight ; histogram counts per dst
__global__ void k_deg(const int* __restrict__ ei, const float* __restrict__ ew) {
    int e = blockIdx.x * blockDim.x + threadIdx.x;
    if (e >= EE) return;
    int dst = ei[EE + e];
    red_add_f32(&g_deg[dst], ew[e]);
    atomicAdd(&g_ecnt[dst], 1);
}

// single-block exclusive scan of 40000 counts (1024 thr x 40 elems) +
// fused deg->rsqrt. Writes g_rs (row starts) and preloads g_fill cursors.
#define PER_T 40
__global__ void k_scan() {
    __shared__ int wsum[32];
    __shared__ int wexc[32];
    const int t = threadIdx.x;
    const int lane = t & 31, wid = t >> 5;
    const int base = t * PER_T;

    int s = 0;
    #pragma unroll
    for (int i = 0; i < PER_T; i++) {
        int idx = base + i;
        s += (idx < NN) ? g_ecnt[idx] : 0;
    }
    // warp inclusive scan of per-thread sums
    int v = s;
    #pragma unroll
    for (int off = 1; off < 32; off <<= 1) {
        int n = __shfl_up_sync(0xffffffffu, v, off);
        if (lane >= off) v += n;
    }
    if (lane == 31) wsum[wid] = v;
    __syncthreads();
    if (wid == 0) {
        int wv = wsum[lane];
        int q = wv;
        #pragma unroll
        for (int off = 1; off < 32; off <<= 1) {
            int n = __shfl_up_sync(0xffffffffu, q, off);
            if (lane >= off) q += n;
        }
        wexc[lane] = q - wv;        // exclusive warp offset
    }
    __syncthreads();

    int run = (v - s) + wexc[wid];  // exclusive prefix for this thread
    #pragma unroll
    for (int i = 0; i < PER_T; i++) {
        int idx = base + i;
        if (idx < NN) {
            g_rs[idx] = run;
            g_fill[idx] = run;
            run += g_ecnt[idx];
        }
    }
    #pragma unroll
    for (int i = 0; i < PER_T; i++) {
        int idx = base + i;
        if (idx < NN) g_deg[idx] = rsqrtf(g_deg[idx]);
    }
    if (t == 0) g_rs[NN] = EE;
}

// scatter edges into CSR slots; one STG.64 per edge {src, norm}
__global__ void k_fill(const int* __restrict__ ei, const float* __restrict__ ew) {
    int e = blockIdx.x * blockDim.x + threadIdx.x;
    if (e >= EE) return;
    int src = ei[e];
    int dst = ei[EE + e];
    float nrm = g_deg[src] * ew[e] * g_deg[dst];
    int pos = atomicAdd(&g_fill[dst], 1);      // cursor preloaded with row start
    g_edge[pos] = make_int2(src, __float_as_int(nrm));
}

// hW = x @ conv_w  (40000x128 @ 128x128, fp32)  [R7 measured-good version]
// block: 256 threads computes 64 rows x 128 cols, full K=128 resident in smem.
__global__ void k_gemm(const float* __restrict__ X, const float* __restrict__ W) {
    extern __shared__ float smem[];
    float* Ws = smem;                   // 128 x 128
    float* xs = smem + 128 * 128;       // 64 x 132 (padded)

    const int tid = threadIdx.x;
    const int row0 = blockIdx.x * 64;

    {
        const float4* Wg = reinterpret_cast<const float4*>(W);
        float4* Ws4 = reinterpret_cast<float4*>(Ws);
        #pragma unroll
        for (int i = 0; i < 16; i++) Ws4[tid + i * 256] = Wg[tid + i * 256];
    }
    {
        const float4* Xg = reinterpret_cast<const float4*>(X + (size_t)row0 * DD);
        #pragma unroll
        for (int i = 0; i < 8; i++) {
            int idx = tid + i * 256;
            int r = idx >> 5, kq = idx & 31;
            reinterpret_cast<float4*>(xs + r * 132)[kq] = Xg[idx];
        }
    }
    __syncthreads();

    const int lane = tid & 31;
    const int wrp = tid >> 5;
    const float* xrow = xs + (wrp * 8) * 132;

    float acc[8][4];
    #pragma unroll
    for (int j = 0; j < 8; j++) { acc[j][0] = acc[j][1] = acc[j][2] = acc[j][3] = 0.f; }

    #pragma unroll 8
    for (int k = 0; k < 128; k++) {
        float4 w4 = reinterpret_cast<const float4*>(Ws + k * 128)[lane];
        #pragma unroll
        for (int j = 0; j < 8; j++) {
            float xv = xrow[j * 132 + k];
            acc[j][0] = fmaf(xv, w4.x, acc[j][0]);
            acc[j][1] = fmaf(xv, w4.y, acc[j][1]);
            acc[j][2] = fmaf(xv, w4.z, acc[j][2]);
            acc[j][3] = fmaf(xv, w4.w, acc[j][3]);
        }
    }

    #pragma unroll
    for (int j = 0; j < 8; j++) {
        int row = row0 + wrp * 8 + j;
        reinterpret_cast<float4*>(g_hW + (size_t)row * DD)[lane] =
            make_float4(acc[j][0], acc[j][1], acc[j][2], acc[j][3]);
    }
}

// fused: CSR gather + self-loop + bias + ReLU + pooled max/sum/cnt.
// one warp per 8 consecutive nodes (batch sorted -> rare flushes).
__device__ __forceinline__ void pool_flush(int g, int lane, float4 pm, float4 ps, int cl) {
    int base = g * DD + lane * 4;
    atomicMax(&g_pmaxi[base + 0], __float_as_int(pm.x));
    atomicMax(&g_pmaxi[base + 1], __float_as_int(pm.y));
    atomicMax(&g_pmaxi[base + 2], __float_as_int(pm.z));
    atomicMax(&g_pmaxi[base + 3], __float_as_int(pm.w));
    red_add_v4(&g_psum[base], ps.x, ps.y, ps.z, ps.w);
    if (lane == 0) red_add_f32(&g_cnt[g], (float)cl);
}

__global__ void k_gather_pool(const float* __restrict__ bias,
                              const int* __restrict__ batchv) {
    int warp = (blockIdx.x * blockDim.x + threadIdx.x) >> 5;
    if (warp >= NN / 8) return;
    const int lane = threadIdx.x & 31;
    const int n0 = warp * 8;

    float4 bia = reinterpret_cast<const float4*>(bias)[lane];
    float4 pm = make_float4(0.f, 0.f, 0.f, 0.f);
    float4 ps = make_float4(0.f, 0.f, 0.f, 0.f);
    int cl = 0;
    int cur_g = batchv[n0];

    #pragma unroll 1
    for (int i = 0; i < 8; i++) {
        int n = n0 + i;
        int g = batchv[n];
        if (g != cur_g) {
            pool_flush(cur_g, lane, pm, ps, cl);
            pm = make_float4(0.f, 0.f, 0.f, 0.f);
            ps = make_float4(0.f, 0.f, 0.f, 0.f);
            cl = 0;
            cur_g = g;
        }
        float dn = g_deg[n];
        float sl = dn * dn;                          // self-loop norm
        float4 h = reinterpret_cast<const float4*>(g_hW + (size_t)n * DD)[lane];
        float4 acc = make_float4(fmaf(h.x, sl, bia.x), fmaf(h.y, sl, bia.y),
                                 fmaf(h.z, sl, bia.z), fmaf(h.w, sl, bia.w));
        int e0 = g_rs[n];
        int e1 = g_rs[n + 1];
        int e = e0;
        for (; e + 4 <= e1; e += 4) {
            int2 p0 = g_edge[e],     p1 = g_edge[e + 1];
            int2 p2 = g_edge[e + 2], p3 = g_edge[e + 3];
            float w0 = __int_as_float(p0.y), w1 = __int_as_float(p1.y);
            float w2 = __int_as_float(p2.y), w3 = __int_as_float(p3.y);
            float4 v0 = reinterpret_cast<const float4*>(g_hW + (size_t)p0.x * DD)[lane];
            float4 v1 = reinterpret_cast<const float4*>(g_hW + (size_t)p1.x * DD)[lane];
            float4 v2 = reinterpret_cast<const float4*>(g_hW + (size_t)p2.x * DD)[lane];
            float4 v3 = reinterpret_cast<const float4*>(g_hW + (size_t)p3.x * DD)[lane];
            acc.x = fmaf(v0.x, w0, fmaf(v1.x, w1, fmaf(v2.x, w2, fmaf(v3.x, w3, acc.x))));
            acc.y = fmaf(v0.y, w0, fmaf(v1.y, w1, fmaf(v2.y, w2, fmaf(v3.y, w3, acc.y))));
            acc.z = fmaf(v0.z, w0, fmaf(v1.z, w1, fmaf(v2.z, w2, fmaf(v3.z, w3, acc.z))));
            acc.w = fmaf(v0.w, w0, fmaf(v1.w, w1, fmaf(v2.w, w2, fmaf(v3.w, w3, acc.w))));
        }
        for (; e < e1; e++) {
            int2 p0 = g_edge[e];
            float w0 = __int_as_float(p0.y);
            float4 v0 = reinterpret_cast<const float4*>(g_hW + (size_t)p0.x * DD)[lane];
            acc.x = fmaf(v0.x, w0, acc.x);
            acc.y = fmaf(v0.y, w0, acc.y);
            acc.z = fmaf(v0.z, w0, acc.z);
            acc.w = fmaf(v0.w, w0, acc.w);
        }
        // ReLU
        acc.x = fmaxf(acc.x, 0.f); acc.y = fmaxf(acc.y, 0.f);
        acc.z = fmaxf(acc.z, 0.f); acc.w = fmaxf(acc.w, 0.f);
        // pool into registers
        pm.x = fmaxf(pm.x, acc.x); pm.y = fmaxf(pm.y, acc.y);
        pm.z = fmaxf(pm.z, acc.z); pm.w = fmaxf(pm.w, acc.w);
        ps.x += acc.x; ps.y += acc.y; ps.z += acc.z; ps.w += acc.w;
        cl++;
    }
    pool_flush(cur_g, lane, pm, ps, cl);
}

// per-graph MLP: one block (128 threads) per graph runs all three layers
__global__ void k_mlp(const float* __restrict__ rho,
                      const float* __restrict__ w1, const float* __restrict__ b1,
                      const float* __restrict__ w2, const float* __restrict__ b2,
                      const float* __restrict__ w3, const float* __restrict__ b3,
                      float* __restrict__ out) {
    __shared__ float hg[260];
    __shared__ float z1[DD];
    __shared__ float z2[DD];
    const int g = blockIdx.x;
    const int t = threadIdx.x;

    float cnt = g_cnt[g];
    float inv = 1.0f / fmaxf(cnt, 1.0f);
    hg[t] = __int_as_float(g_pmaxi[g * DD + t]);
    hg[DD + t] = g_psum[g * DD + t] * inv;
    if (t == 0) hg[2 * DD] = rho[g];
    __syncthreads();

    float acc = b1[t];
    #pragma unroll 8
    for (int k = 0; k < 2 * DD + 1; k++) acc = fmaf(hg[k], w1[k * DD + t], acc);
    z1[t] = fmaxf(acc, 0.f);
    __syncthreads();

    acc = b2[t];
    #pragma unroll 8
    for (int k = 0; k < DD; k++) acc = fmaf(z1[k], w2[k * DD + t], acc);
    z2[t] = fmaxf(acc, 0.f);
    __syncthreads();

    if (t < DOUT) {
        acc = b3[t];
        #pragma unroll 8
        for (int k = 0; k < DD; k++) acc = fmaf(z2[k], w3[k * DOUT + t], acc);
        out[g * DOUT + t] = acc;
    }
}

// ---------------- launch -----------------------------------------------------
extern "C" void kernel_launch(void* const* d_in, const int* in_sizes, int n_in,
                              void* d_out, int out_size) {
    const float* x      = (const float*)d_in[0];
    const float* ew     = (const float*)d_in[1];
    const float* rho    = (const float*)d_in[2];
    const float* conv_w = (const float*)d_in[3];
    const float* conv_b = (const float*)d_in[4];
    const float* w1     = (const float*)d_in[5];
    const float* b1     = (const float*)d_in[6];
    const float* w2     = (const float*)d_in[7];
    const float* b2     = (const float*)d_in[8];
    const float* w3     = (const float*)d_in[9];
    const float* b3     = (const float*)d_in[10];
    const int*   ei     = (const int*)d_in[11];
    const int*   batchv = (const int*)d_in[12];
    float* out = (float*)d_out;

    const int gemm_smem = (128 * 128 + 64 * 132) * 4;   // 99328 B
    cudaFuncSetAttribute(k_gemm, cudaFuncAttributeMaxDynamicSharedMemorySize, gemm_smem);

    // reset state
    k_init<<<(NN + 255) / 256, 256>>>();
    // degree + histogram
    k_deg<<<(EE + 255) / 256, 256>>>(ei, ew);
    // single-block scan (also fuses deg->rsqrt, preloads fill cursors)
    k_scan<<<1, 1024>>>();
    // CSR fill with precomputed norms (packed int2 slots)
    k_fill<<<(EE + 255) / 256, 256>>>(ei, ew);
    // hW = x @ conv_w (measured-good R7 GEMM)
    k_gemm<<<NN / 64, 256, gemm_smem>>>(x, conv_w);
    // fused gather + relu + pool
    k_gather_pool<<<(NN / 8 * 32 + 255) / 256, 256>>>(conv_b, batchv);
    // MLP head
    k_mlp<<<GG, DD>>>(rho, w1, b1, w2, b2, w3, b3, out);
}

// round 14
// speedup vs baseline: 1.4724x; 1.4387x over previous
#include <cuda_runtime.h>
#include <cuda_bf16.h>
#include <cstdint>

// Problem constants (match reference setup_inputs)
#define NN 40000
#define EE 640000
#define GG 64
#define DD 128          // D_IN = D_EMB = D_HID
#define DOUT 36
#define SCAN_BLK 1024
#define NSCAN ((NN + SCAN_BLK - 1) / SCAN_BLK)   // 40

// ---------------- scratch (device globals; no allocation allowed) -----------
__device__ __align__(16) float g_deg[NN];          // degree, then rsqrt in place
__device__ __align__(16) float g_hW[(size_t)NN * DD];
__device__ __align__(16) int   g_ecnt[NN];         // per-dst edge count
__device__ __align__(16) int   g_fill[NN];         // fill cursors (zeroed)
__device__ __align__(16) int   g_rs[NN];           // exclusive scan (per-block partial)
__device__ int   g_bsum[NSCAN];
__device__ int   g_boff[64];                       // scanned block offsets
__device__ __align__(16) int2  g_edge[EE];         // CSR: {src, norm bits} per slot
__device__ __align__(16) int   g_pmaxi[GG * DD];   // float bits, values >= 0
__device__ __align__(16) float g_psum[GG * DD];
__device__ float g_cnt[GG];

// ---------------- helpers ---------------------------------------------------
__device__ __forceinline__ void red_add_v4(float* p, float a, float b, float c, float d) {
    asm volatile("red.global.add.v4.f32 [%0], {%1, %2, %3, %4};"
                 :: "l"(p), "f"(a), "f"(b), "f"(c), "f"(d) : "memory");
}
__device__ __forceinline__ void red_add_f32(float* p, float v) {
    asm volatile("red.global.add.f32 [%0], %1;" :: "l"(p), "f"(v) : "memory");
}
// row start with block offset folded in (avoids a 3rd scan pass)
__device__ __forceinline__ int row_start(int i) {
    return (i < NN) ? (g_rs[i] + g_boff[i >> 10]) : EE;
}

// ---------------- kernels ---------------------------------------------------

// reset all per-call state
__global__ void k_init() {
    int i = blockIdx.x * blockDim.x + threadIdx.x;
    if (i < NN) { g_deg[i] = 1.0f; g_ecnt[i] = 0; g_fill[i] = 0; }
    if (i < GG * DD) { g_pmaxi[i] = 0; g_psum[i] = 0.0f; }
    if (i < GG) g_cnt[i] = 0.0f;
}

// deg[dst] += edge_weight ; histogram counts per dst
__global__ void k_deg(const int* __restrict__ ei, const float* __restrict__ ew) {
    int e = blockIdx.x * blockDim.x + threadIdx.x;
    if (e >= EE) return;
    int dst = ei[EE + e];
    red_add_f32(&g_deg[dst], ew[e]);
    atomicAdd(&g_ecnt[dst], 1);
}

// per-block exclusive scan of counts + fused deg->rsqrt(deg)  [R7 measured-good]
__global__ void k_scan1() {
    __shared__ int s[SCAN_BLK];
    int t = threadIdx.x;
    int idx = blockIdx.x * SCAN_BLK + t;
    int c = (idx < NN) ? g_ecnt[idx] : 0;
    s[t] = c;
    __syncthreads();
    #pragma unroll
    for (int off = 1; off < SCAN_BLK; off <<= 1) {
        int v = (t >= off) ? s[t - off] : 0;
        __syncthreads();
        s[t] += v;
        __syncthreads();
    }
    if (idx < NN) g_rs[idx] = s[t] - c;         // exclusive within block
    if (t == SCAN_BLK - 1) g_bsum[blockIdx.x] = s[t];
    if (idx < NN) g_deg[idx] = rsqrtf(g_deg[idx]);
}

// scan the 40 block sums (single block, 64 threads)
__global__ void k_scan2() {
    __shared__ int s[64];
    int t = threadIdx.x;
    int c = (t < NSCAN) ? g_bsum[t] : 0;
    s[t] = c;
    __syncthreads();
    #pragma unroll
    for (int off = 1; off < 64; off <<= 1) {
        int v = (t >= off) ? s[t - off] : 0;
        __syncthreads();
        s[t] += v;
        __syncthreads();
    }
    g_boff[t] = s[t] - c;                       // exclusive
}

// scatter edges into CSR slots; one STG.64 per edge {src, norm}
__global__ void k_fill(const int* __restrict__ ei, const float* __restrict__ ew) {
    int e = blockIdx.x * blockDim.x + threadIdx.x;
    if (e >= EE) return;
    int src = ei[e];
    int dst = ei[EE + e];
    float nrm = g_deg[src] * ew[e] * g_deg[dst];
    int pos = row_start(dst) + atomicAdd(&g_fill[dst], 1);
    g_edge[pos] = make_int2(src, __float_as_int(nrm));
}

// hW = x @ conv_w  (40000x128 @ 128x128, fp32)  [R7 measured-good version]
__global__ void k_gemm(const float* __restrict__ X, const float* __restrict__ W) {
    extern __shared__ float smem[];
    float* Ws = smem;                   // 128 x 128
    float* xs = smem + 128 * 128;       // 64 x 132 (padded)

    const int tid = threadIdx.x;
    const int row0 = blockIdx.x * 64;

    {
        const float4* Wg = reinterpret_cast<const float4*>(W);
        float4* Ws4 = reinterpret_cast<float4*>(Ws);
        #pragma unroll
        for (int i = 0; i < 16; i++) Ws4[tid + i * 256] = Wg[tid + i * 256];
    }
    {
        const float4* Xg = reinterpret_cast<const float4*>(X + (size_t)row0 * DD);
        #pragma unroll
        for (int i = 0; i < 8; i++) {
            int idx = tid + i * 256;
            int r = idx >> 5, kq = idx & 31;
            reinterpret_cast<float4*>(xs + r * 132)[kq] = Xg[idx];
        }
    }
    __syncthreads();

    const int lane = tid & 31;
    const int wrp = tid >> 5;
    const float* xrow = xs + (wrp * 8) * 132;

    float acc[8][4];
    #pragma unroll
    for (int j = 0; j < 8; j++) { acc[j][0] = acc[j][1] = acc[j][2] = acc[j][3] = 0.f; }

    #pragma unroll 8
    for (int k = 0; k < 128; k++) {
        float4 w4 = reinterpret_cast<const float4*>(Ws + k * 128)[lane];
        #pragma unroll
        for (int j = 0; j < 8; j++) {
            float xv = xrow[j * 132 + k];
            acc[j][0] = fmaf(xv, w4.x, acc[j][0]);
            acc[j][1] = fmaf(xv, w4.y, acc[j][1]);
            acc[j][2] = fmaf(xv, w4.z, acc[j][2]);
            acc[j][3] = fmaf(xv, w4.w, acc[j][3]);
        }
    }

    #pragma unroll
    for (int j = 0; j < 8; j++) {
        int row = row0 + wrp * 8 + j;
        reinterpret_cast<float4*>(g_hW + (size_t)row * DD)[lane] =
            make_float4(acc[j][0], acc[j][1], acc[j][2], acc[j][3]);
    }
}

// fused: CSR gather + self-loop + bias + ReLU + pooled max/sum/cnt.
// one warp per 8 consecutive nodes (batch sorted -> rare flushes).
__device__ __forceinline__ void pool_flush(int g, int lane, float4 pm, float4 ps, int cl) {
    int base = g * DD + lane * 4;
    atomicMax(&g_pmaxi[base + 0], __float_as_int(pm.x));
    atomicMax(&g_pmaxi[base + 1], __float_as_int(pm.y));
    atomicMax(&g_pmaxi[base + 2], __float_as_int(pm.z));
    atomicMax(&g_pmaxi[base + 3], __float_as_int(pm.w));
    red_add_v4(&g_psum[base], ps.x, ps.y, ps.z, ps.w);
    if (lane == 0) red_add_f32(&g_cnt[g], (float)cl);
}

__global__ void k_gather_pool(const float* __restrict__ bias,
                              const int* __restrict__ batchv) {
    int warp = (blockIdx.x * blockDim.x + threadIdx.x) >> 5;
    if (warp >= NN / 8) return;
    const int lane = threadIdx.x & 31;
    const int n0 = warp * 8;

    float4 bia = reinterpret_cast<const float4*>(bias)[lane];
    float4 pm = make_float4(0.f, 0.f, 0.f, 0.f);
    float4 ps = make_float4(0.f, 0.f, 0.f, 0.f);
    int cl = 0;
    int cur_g = batchv[n0];

    int e1 = row_start(n0);                      // rolls into e0 each iteration

    #pragma unroll 1
    for (int i = 0; i < 8; i++) {
        int n = n0 + i;
        int g = batchv[n];
        if (g != cur_g) {
            pool_flush(cur_g, lane, pm, ps, cl);
            pm = make_float4(0.f, 0.f, 0.f, 0.f);
            ps = make_float4(0.f, 0.f, 0.f, 0.f);
            cl = 0;
            cur_g = g;
        }
        float dn = g_deg[n];
        float sl = dn * dn;                          // self-loop norm
        float4 h = reinterpret_cast<const float4*>(g_hW + (size_t)n * DD)[lane];
        float4 acc = make_float4(fmaf(h.x, sl, bia.x), fmaf(h.y, sl, bia.y),
                                 fmaf(h.z, sl, bia.z), fmaf(h.w, sl, bia.w));
        int e = e1;
        e1 = row_start(n + 1);
        for (; e + 4 <= e1; e += 4) {
            int2 p0 = g_edge[e],     p1 = g_edge[e + 1];
            int2 p2 = g_edge[e + 2], p3 = g_edge[e + 3];
            float w0 = __int_as_float(p0.y), w1 = __int_as_float(p1.y);
            float w2 = __int_as_float(p2.y), w3 = __int_as_float(p3.y);
            float4 v0 = reinterpret_cast<const float4*>(g_hW + (size_t)p0.x * DD)[lane];
            float4 v1 = reinterpret_cast<const float4*>(g_hW + (size_t)p1.x * DD)[lane];
            float4 v2 = reinterpret_cast<const float4*>(g_hW + (size_t)p2.x * DD)[lane];
            float4 v3 = reinterpret_cast<const float4*>(g_hW + (size_t)p3.x * DD)[lane];
            acc.x = fmaf(v0.x, w0, fmaf(v1.x, w1, fmaf(v2.x, w2, fmaf(v3.x, w3, acc.x))));
            acc.y = fmaf(v0.y, w0, fmaf(v1.y, w1, fmaf(v2.y, w2, fmaf(v3.y, w3, acc.y))));
            acc.z = fmaf(v0.z, w0, fmaf(v1.z, w1, fmaf(v2.z, w2, fmaf(v3.z, w3, acc.z))));
            acc.w = fmaf(v0.w, w0, fmaf(v1.w, w1, fmaf(v2.w, w2, fmaf(v3.w, w3, acc.w))));
        }
        for (; e < e1; e++) {
            int2 p0 = g_edge[e];
            float w0 = __int_as_float(p0.y);
            float4 v0 = reinterpret_cast<const float4*>(g_hW + (size_t)p0.x * DD)[lane];
            acc.x = fmaf(v0.x, w0, acc.x);
            acc.y = fmaf(v0.y, w0, acc.y);
            acc.z = fmaf(v0.z, w0, acc.z);
            acc.w = fmaf(v0.w, w0, acc.w);
        }
        // ReLU
        acc.x = fmaxf(acc.x, 0.f); acc.y = fmaxf(acc.y, 0.f);
        acc.z = fmaxf(acc.z, 0.f); acc.w = fmaxf(acc.w, 0.f);
        // pool into registers
        pm.x = fmaxf(pm.x, acc.x); pm.y = fmaxf(pm.y, acc.y);
        pm.z = fmaxf(pm.z, acc.z); pm.w = fmaxf(pm.w, acc.w);
        ps.x += acc.x; ps.y += acc.y; ps.z += acc.z; ps.w += acc.w;
        cl++;
    }
    pool_flush(cur_g, lane, pm, ps, cl);
}

// per-graph MLP: one block (128 threads) per graph runs all three layers
__global__ void k_mlp(const float* __restrict__ rho,
                      const float* __restrict__ w1, const float* __restrict__ b1,
                      const float* __restrict__ w2, const float* __restrict__ b2,
                      const float* __restrict__ w3, const float* __restrict__ b3,
                      float* __restrict__ out) {
    __shared__ float hg[260];
    __shared__ float z1[DD];
    __shared__ float z2[DD];
    const int g = blockIdx.x;
    const int t = threadIdx.x;

    float cnt = g_cnt[g];
    float inv = 1.0f / fmaxf(cnt, 1.0f);
    hg[t] = __int_as_float(g_pmaxi[g * DD + t]);
    hg[DD + t] = g_psum[g * DD + t] * inv;
    if (t == 0) hg[2 * DD] = rho[g];
    __syncthreads();

    float acc = b1[t];
    #pragma unroll 8
    for (int k = 0; k < 2 * DD + 1; k++) acc = fmaf(hg[k], w1[k * DD + t], acc);
    z1[t] = fmaxf(acc, 0.f);
    __syncthreads();

    acc = b2[t];
    #pragma unroll 8
    for (int k = 0; k < DD; k++) acc = fmaf(z1[k], w2[k * DD + t], acc);
    z2[t] = fmaxf(acc, 0.f);
    __syncthreads();

    if (t < DOUT) {
        acc = b3[t];
        #pragma unroll 8
        for (int k = 0; k < DD; k++) acc = fmaf(z2[k], w3[k * DOUT + t], acc);
        out[g * DOUT + t] = acc;
    }
}

// ---------------- launch -----------------------------------------------------
extern "C" void kernel_launch(void* const* d_in, const int* in_sizes, int n_in,
                              void* d_out, int out_size) {
    const float* x      = (const float*)d_in[0];
    const float* ew     = (const float*)d_in[1];
    const float* rho    = (const float*)d_in[2];
    const float* conv_w = (const float*)d_in[3];
    const float* conv_b = (const float*)d_in[4];
    const float* w1     = (const float*)d_in[5];
    const float* b1     = (const float*)d_in[6];
    const float* w2     = (const float*)d_in[7];
    const float* b2     = (const float*)d_in[8];
    const float* w3     = (const float*)d_in[9];
    const float* b3     = (const float*)d_in[10];
    const int*   ei     = (const int*)d_in[11];
    const int*   batchv = (const int*)d_in[12];
    float* out = (float*)d_out;

    const int gemm_smem = (128 * 128 + 64 * 132) * 4;   // 99328 B
    cudaFuncSetAttribute(k_gemm, cudaFuncAttributeMaxDynamicSharedMemorySize, gemm_smem);

    // reset state
    k_init<<<(NN + 255) / 256, 256>>>();
    // degree + histogram
    k_deg<<<(EE + 255) / 256, 256>>>(ei, ew);
    // parallel block scans (scan1 also fuses deg -> rsqrt)
    k_scan1<<<NSCAN, SCAN_BLK>>>();
    k_scan2<<<1, 64>>>();
    // CSR fill with precomputed norms (packed int2 slots)
    k_fill<<<(EE + 255) / 256, 256>>>(ei, ew);
    // hW = x @ conv_w (measured-good R7 GEMM)
    k_gemm<<<NN / 64, 256, gemm_smem>>>(x, conv_w);
    // fused gather + relu + pool
    k_gather_pool<<<(NN / 8 * 32 + 255) / 256, 256>>>(conv_b, batchv);
    // MLP head
    k_mlp<<<GG, DD>>>(rho, w1, b1, w2, b2, w3, b3, out);
}

// round 17
// speedup vs baseline: 1.7677x; 1.2006x over previous
#include <cuda_runtime.h>
#include <cuda_fp16.h>
#include <cstdint>

// Problem constants (match reference setup_inputs)
#define NN 40000
#define EE 640000
#define GG 64
#define DD 128          // D_IN = D_EMB = D_HID
#define DOUT 36
#define SCAN_BLK 1024
#define NSCAN ((NN + SCAN_BLK - 1) / SCAN_BLK)   // 40

// ---------------- scratch (device globals; no allocation allowed) -----------
__device__ __align__(16) unsigned long long g_dc[NN];  // packed: count<<40 | deg*2^24
__device__ __align__(16) float g_deg[NN];          // rsqrt(deg) after scan1
__device__ __align__(16) float g_hW[(size_t)NN * DD];       // fp32 (self-loop path)
__device__ __align__(16) __half g_hWh[(size_t)NN * DD];     // fp16 copy (gather path)
__device__ __align__(16) int   g_fill[NN];         // fill cursors (zeroed)
__device__ __align__(16) int   g_rs[NN];           // exclusive scan (per-block partial)
__device__ int   g_bsum[NSCAN];
__device__ int   g_boff[64];                       // scanned block offsets
__device__ __align__(16) int2  g_edge[EE];         // CSR: {src, norm bits} per slot
__device__ __align__(16) int   g_pmaxi[GG * DD];   // float bits, values >= 0
__device__ __align__(16) float g_psum[GG * DD];
__device__ float g_cnt[GG];

#define DEG_MASK ((1ull << 40) - 1ull)
#define DEG_SCALE 16777216.0f          // 2^24

// ---------------- helpers ---------------------------------------------------
__device__ __forceinline__ void red_add_v4(float* p, float a, float b, float c, float d) {
    asm volatile("red.global.add.v4.f32 [%0], {%1, %2, %3, %4};"
                 :: "l"(p), "f"(a), "f"(b), "f"(c), "f"(d) : "memory");
}
__device__ __forceinline__ void red_add_f32(float* p, float v) {
    asm volatile("red.global.add.f32 [%0], %1;" :: "l"(p), "f"(v) : "memory");
}
// row start with block offset folded in (avoids a 3rd scan pass)
__device__ __forceinline__ int row_start(int i) {
    return (i < NN) ? (g_rs[i] + g_boff[i >> 10]) : EE;
}

// ---------------- kernels ---------------------------------------------------

// reset all per-call state
__global__ void k_init() {
    int i = blockIdx.x * blockDim.x + threadIdx.x;
    if (i < NN) {
        g_dc[i] = (unsigned long long)(1.0f * DEG_SCALE);  // deg=1 (self loop), count=0
        g_fill[i] = 0;
    }
    if (i < GG * DD) { g_pmaxi[i] = 0; g_psum[i] = 0.0f; }
    if (i < GG) g_cnt[i] = 0.0f;
}

// ONE u64 atomic per edge: count<<40 | deg_fixedpoint
__global__ void k_deg(const int* __restrict__ ei, const float* __restrict__ ew) {
    int e = blockIdx.x * blockDim.x + threadIdx.x;
    if (e >= EE) return;
    int dst = ei[EE + e];
    unsigned long long v = (1ull << 40) |
        (unsigned long long)__float2uint_rn(ew[e] * DEG_SCALE);
    atomicAdd(&g_dc[dst], v);
}

// per-block exclusive scan of counts + fused deg->rsqrt(deg)
__global__ void k_scan1() {
    __shared__ int s[SCAN_BLK];
    int t = threadIdx.x;
    int idx = blockIdx.x * SCAN_BLK + t;
    unsigned long long v = (idx < NN) ? g_dc[idx] : 0ull;
    int c = (int)(v >> 40);
    s[t] = c;
    __syncthreads();
    #pragma unroll
    for (int off = 1; off < SCAN_BLK; off <<= 1) {
        int p = (t >= off) ? s[t - off] : 0;
        __syncthreads();
        s[t] += p;
        __syncthreads();
    }
    if (idx < NN) g_rs[idx] = s[t] - c;         // exclusive within block
    if (t == SCAN_BLK - 1) g_bsum[blockIdx.x] = s[t];
    if (idx < NN) {
        float deg = (float)(v & DEG_MASK) * (1.0f / DEG_SCALE);
        g_deg[idx] = rsqrtf(deg);
    }
}

// scan the 40 block sums (single block, 64 threads)
__global__ void k_scan2() {
    __shared__ int s[64];
    int t = threadIdx.x;
    int c = (t < NSCAN) ? g_bsum[t] : 0;
    s[t] = c;
    __syncthreads();
    #pragma unroll
    for (int off = 1; off < 64; off <<= 1) {
        int v = (t >= off) ? s[t - off] : 0;
        __syncthreads();
        s[t] += v;
        __syncthreads();
    }
    g_boff[t] = s[t] - c;                       // exclusive
}

// scatter edges into CSR slots; one STG.64 per edge {src, norm}
__global__ void k_fill(const int* __restrict__ ei, const float* __restrict__ ew) {
    int e = blockIdx.x * blockDim.x + threadIdx.x;
    if (e >= EE) return;
    int src = ei[e];
    int dst = ei[EE + e];
    float nrm = g_deg[src] * ew[e] * g_deg[dst];
    int pos = row_start(dst) + atomicAdd(&g_fill[dst], 1);
    g_edge[pos] = make_int2(src, __float_as_int(nrm));
}

// hW = x @ conv_w  (40000x128 @ 128x128, fp32)  [R7 measured-good version]
// epilogue additionally writes an fp16 copy for the gather path.
__global__ void k_gemm(const float* __restrict__ X, const float* __restrict__ W) {
    extern __shared__ float smem[];
    float* Ws = smem;                   // 128 x 128
    float* xs = smem + 128 * 128;       // 64 x 132 (padded)

    const int tid = threadIdx.x;
    const int row0 = blockIdx.x * 64;

    {
        const float4* Wg = reinterpret_cast<const float4*>(W);
        float4* Ws4 = reinterpret_cast<float4*>(Ws);
        #pragma unroll
        for (int i = 0; i < 16; i++) Ws4[tid + i * 256] = Wg[tid + i * 256];
    }
    {
        const float4* Xg = reinterpret_cast<const float4*>(X + (size_t)row0 * DD);
        #pragma unroll
        for (int i = 0; i < 8; i++) {
            int idx = tid + i * 256;
            int r = idx >> 5, kq = idx & 31;
            reinterpret_cast<float4*>(xs + r * 132)[kq] = Xg[idx];
        }
    }
    __syncthreads();

    const int lane = tid & 31;
    const int wrp = tid >> 5;
    const float* xrow = xs + (wrp * 8) * 132;

    float acc[8][4];
    #pragma unroll
    for (int j = 0; j < 8; j++) { acc[j][0] = acc[j][1] = acc[j][2] = acc[j][3] = 0.f; }

    #pragma unroll 8
    for (int k = 0; k < 128; k++) {
        float4 w4 = reinterpret_cast<const float4*>(Ws + k * 128)[lane];
        #pragma unroll
        for (int j = 0; j < 8; j++) {
            float xv = xrow[j * 132 + k];
            acc[j][0] = fmaf(xv, w4.x, acc[j][0]);
            acc[j][1] = fmaf(xv, w4.y, acc[j][1]);
            acc[j][2] = fmaf(xv, w4.z, acc[j][2]);
            acc[j][3] = fmaf(xv, w4.w, acc[j][3]);
        }
    }

    #pragma unroll
    for (int j = 0; j < 8; j++) {
        int row = row0 + wrp * 8 + j;
        reinterpret_cast<float4*>(g_hW + (size_t)row * DD)[lane] =
            make_float4(acc[j][0], acc[j][1], acc[j][2], acc[j][3]);
        // fp16 copy (cols 4*lane..4*lane+3 -> one 8-byte store)
        __half2 h01 = __floats2half2_rn(acc[j][0], acc[j][1]);
        __half2 h23 = __floats2half2_rn(acc[j][2], acc[j][3]);
        uint2 u;
        u.x = *reinterpret_cast<unsigned*>(&h01);
        u.y = *reinterpret_cast<unsigned*>(&h23);
        reinterpret_cast<uint2*>(g_hWh + (size_t)row * DD)[lane] = u;
    }
}

// fused: CSR gather (fp16 payload) + self-loop (fp32) + bias + ReLU + pool.
// one warp per 8 consecutive nodes (batch sorted -> rare flushes).
__device__ __forceinline__ void pool_flush(int g, int lane, float4 pm, float4 ps, int cl) {
    int base = g * DD + lane * 4;
    atomicMax(&g_pmaxi[base + 0], __float_as_int(pm.x));
    atomicMax(&g_pmaxi[base + 1], __float_as_int(pm.y));
    atomicMax(&g_pmaxi[base + 2], __float_as_int(pm.z));
    atomicMax(&g_pmaxi[base + 3], __float_as_int(pm.w));
    red_add_v4(&g_psum[base], ps.x, ps.y, ps.z, ps.w);
    if (lane == 0) red_add_f32(&g_cnt[g], (float)cl);
}

__device__ __forceinline__ void fma_h(float4& acc, uint2 u, float w) {
    float2 a = __half22float2(*reinterpret_cast<__half2*>(&u.x));
    float2 b = __half22float2(*reinterpret_cast<__half2*>(&u.y));
    acc.x = fmaf(a.x, w, acc.x);
    acc.y = fmaf(a.y, w, acc.y);
    acc.z = fmaf(b.x, w, acc.z);
    acc.w = fmaf(b.y, w, acc.w);
}

__global__ void k_gather_pool(const float* __restrict__ bias,
                              const int* __restrict__ batchv) {
    int warp = (blockIdx.x * blockDim.x + threadIdx.x) >> 5;
    if (warp >= NN / 8) return;
    const int lane = threadIdx.x & 31;
    const int n0 = warp * 8;

    float4 bia = reinterpret_cast<const float4*>(bias)[lane];
    float4 pm = make_float4(0.f, 0.f, 0.f, 0.f);
    float4 ps = make_float4(0.f, 0.f, 0.f, 0.f);
    int cl = 0;
    int cur_g = batchv[n0];

    int e1 = row_start(n0);                      // rolls into e0 each iteration

    #pragma unroll 1
    for (int i = 0; i < 8; i++) {
        int n = n0 + i;
        int g = batchv[n];
        if (g != cur_g) {
            pool_flush(cur_g, lane, pm, ps, cl);
            pm = make_float4(0.f, 0.f, 0.f, 0.f);
            ps = make_float4(0.f, 0.f, 0.f, 0.f);
            cl = 0;
            cur_g = g;
        }
        float dn = g_deg[n];
        float sl = dn * dn;                          // self-loop norm
        float4 h = reinterpret_cast<const float4*>(g_hW + (size_t)n * DD)[lane];
        float4 acc = make_float4(fmaf(h.x, sl, bia.x), fmaf(h.y, sl, bia.y),
                                 fmaf(h.z, sl, bia.z), fmaf(h.w, sl, bia.w));
        int e = e1;
        e1 = row_start(n + 1);
        for (; e + 4 <= e1; e += 4) {
            int2 p0 = g_edge[e],     p1 = g_edge[e + 1];
            int2 p2 = g_edge[e + 2], p3 = g_edge[e + 3];
            uint2 u0 = reinterpret_cast<const uint2*>(g_hWh + (size_t)p0.x * DD)[lane];
            uint2 u1 = reinterpret_cast<const uint2*>(g_hWh + (size_t)p1.x * DD)[lane];
            uint2 u2 = reinterpret_cast<const uint2*>(g_hWh + (size_t)p2.x * DD)[lane];
            uint2 u3 = reinterpret_cast<const uint2*>(g_hWh + (size_t)p3.x * DD)[lane];
            fma_h(acc, u0, __int_as_float(p0.y));
            fma_h(acc, u1, __int_as_float(p1.y));
            fma_h(acc, u2, __int_as_float(p2.y));
            fma_h(acc, u3, __int_as_float(p3.y));
        }
        for (; e < e1; e++) {
            int2 p0 = g_edge[e];
            uint2 u0 = reinterpret_cast<const uint2*>(g_hWh + (size_t)p0.x * DD)[lane];
            fma_h(acc, u0, __int_as_float(p0.y));
        }
        // ReLU
        acc.x = fmaxf(acc.x, 0.f); acc.y = fmaxf(acc.y, 0.f);
        acc.z = fmaxf(acc.z, 0.f); acc.w = fmaxf(acc.w, 0.f);
        // pool into registers
        pm.x = fmaxf(pm.x, acc.x); pm.y = fmaxf(pm.y, acc.y);
        pm.z = fmaxf(pm.z, acc.z); pm.w = fmaxf(pm.w, acc.w);
        ps.x += acc.x; ps.y += acc.y; ps.z += acc.z; ps.w += acc.w;
        cl++;
    }
    pool_flush(cur_g, lane, pm, ps, cl);
}

// per-graph MLP: one block (128 threads) per graph runs all three layers
__global__ void k_mlp(const float* __restrict__ rho,
                      const float* __restrict__ w1, const float* __restrict__ b1,
                      const float* __restrict__ w2, const float* __restrict__ b2,
                      const float* __restrict__ w3, const float* __restrict__ b3,
                      float* __restrict__ out) {
    __shared__ float hg[260];
    __shared__ float z1[DD];
    __shared__ float z2[DD];
    const int g = blockIdx.x;
    const int t = threadIdx.x;

    float cnt = g_cnt[g];
    float inv = 1.0f / fmaxf(cnt, 1.0f);
    hg[t] = __int_as_float(g_pmaxi[g * DD + t]);
    hg[DD + t] = g_psum[g * DD + t] * inv;
    if (t == 0) hg[2 * DD] = rho[g];
    __syncthreads();

    float acc = b1[t];
    #pragma unroll 8
    for (int k = 0; k < 2 * DD + 1; k++) acc = fmaf(hg[k], w1[k * DD + t], acc);
    z1[t] = fmaxf(acc, 0.f);
    __syncthreads();

    acc = b2[t];
    #pragma unroll 8
    for (int k = 0; k < DD; k++) acc = fmaf(z1[k], w2[k * DD + t], acc);
    z2[t] = fmaxf(acc, 0.f);
    __syncthreads();

    if (t < DOUT) {
        acc = b3[t];
        #pragma unroll 8
        for (int k = 0; k < DD; k++) acc = fmaf(z2[k], w3[k * DOUT + t], acc);
        out[g * DOUT + t] = acc;
    }
}

// ---------------- launch -----------------------------------------------------
extern "C" void kernel_launch(void* const* d_in, const int* in_sizes, int n_in,
                              void* d_out, int out_size) {
    const float* x      = (const float*)d_in[0];
    const float* ew     = (const float*)d_in[1];
    const float* rho    = (const float*)d_in[2];
    const float* conv_w = (const float*)d_in[3];
    const float* conv_b = (const float*)d_in[4];
    const float* w1     = (const float*)d_in[5];
    const float* b1     = (const float*)d_in[6];
    const float* w2     = (const float*)d_in[7];
    const float* b2     = (const float*)d_in[8];
    const float* w3     = (const float*)d_in[9];
    const float* b3     = (const float*)d_in[10];
    const int*   ei     = (const int*)d_in[11];
    const int*   batchv = (const int*)d_in[12];
    float* out = (float*)d_out;

    const int gemm_smem = (128 * 128 + 64 * 132) * 4;   // 99328 B
    cudaFuncSetAttribute(k_gemm, cudaFuncAttributeMaxDynamicSharedMemorySize, gemm_smem);

    // reset state
    k_init<<<(NN + 255) / 256, 256>>>();
    // degree + histogram (single fused u64 atomic per edge)
    k_deg<<<(EE + 255) / 256, 256>>>(ei, ew);
    // parallel block scans (scan1 also decodes deg -> rsqrt)
    k_scan1<<<NSCAN, SCAN_BLK>>>();
    k_scan2<<<1, 64>>>();
    // CSR fill with precomputed norms (packed int2 slots)
    k_fill<<<(EE + 255) / 256, 256>>>(ei, ew);
    // hW = x @ conv_w (fp32 + fp16 copy)
    k_gemm<<<NN / 64, 256, gemm_smem>>>(x, conv_w);
    // fused gather (fp16 payload) + relu + pool
    k_gather_pool<<<(NN / 8 * 32 + 255) / 256, 256>>>(conv_b, batchv);
    // MLP head
    k_mlp<<<GG, DD>>>(rho, w1, b1, w2, b2, w3, b3, out);
}